// round 15
// baseline (speedup 1.0000x reference)
#include <cuda_runtime.h>
#include <cuda_fp16.h>
#include <cstdint>

// ---------------------------------------------------------------------------
// GCN pipeline (S = D^-1/2 (A+I) D^-1/2):
//  L1 (commuted): xah = fp16(S·X) padded K=80 ; a1 = xah@W1 + b1 (fp16 MMA)
//  L2: h2 = relu(a1)@W2 * dinv (fp16 MMA) -> g_h
//  L3 FUSED: per 64-node block: gather a2 = dinv*sum(h2)+b2, relu, fp16 ->
//            SMEM A-tile -> K=256 MMA vs W3 -> g_a = h3*dinv (fp16).
//            Full-width 64x256 tile => gather done exactly once per node.
//  L4 folded + fused with L3 agg (gemv4f reads g_a), then mean-pool + head.
// Structure reverted to R13 (R14's launch merges regressed).
// ---------------------------------------------------------------------------

#define MAXN 100000
#define MAXE 400000
#define HID  256
#define K1P  80
#define MAXG 4096
#define SCHUNK 2048

__device__ __half g_h[(size_t)MAXN * HID];
__device__ __half g_a[(size_t)MAXN * HID];
__device__ __half g_wh[(size_t)HID * HID];
__device__ __half g_xah[(size_t)MAXN * K1P];
__device__ float  g_hs2[(size_t)MAXN * 2];
__device__ float  g_dinv[MAXN];
__device__ int    g_deg[MAXN];
__device__ int    g_ptr[MAXN + 1];
__device__ int    g_cur[MAXN];
__device__ int    g_csrc[MAXE];
__device__ int    g_bsum[256];
__device__ float  g_w4l[HID * 2 + 2];
__device__ float  g_pool[(size_t)MAXG * 2];
__device__ float  g_cnt[MAXG];

// ---------------- CSR build (R13 version) ----------------
__global__ void k_zero_deg(int N) {
    int i = blockIdx.x * blockDim.x + threadIdx.x;
    if (i < N) g_deg[i] = 0;
}
__global__ void k_count_deg(const int* __restrict__ dst, int E, int N) {
    int e = blockIdx.x * blockDim.x + threadIdx.x;
    if (e < E) {
        unsigned d = (unsigned)dst[e];
        if (d < (unsigned)N) atomicAdd(&g_deg[d], 1);
    }
}
__global__ void k_scan1(int N) {
    __shared__ int sh[256];
    const int tid = threadIdx.x;
    const int base = blockIdx.x * SCHUNK + tid * 8;
    int s = 0;
#pragma unroll
    for (int i = 0; i < 8; i++) {
        int idx = base + i;
        if (idx < N) {
            int d = g_deg[idx];
            s += d;
            g_dinv[idx] = rsqrtf((float)d + 1.f);
        }
    }
    sh[tid] = s;
    __syncthreads();
    for (int off = 1; off < 256; off <<= 1) {
        int v = (tid >= off) ? sh[tid - off] : 0;
        __syncthreads();
        sh[tid] += v;
        __syncthreads();
    }
    if (tid == 255) g_bsum[blockIdx.x] = sh[255];
}
__global__ void k_scan2(int nb) {
    __shared__ int sh[256];
    const int tid = threadIdx.x;
    int v = (tid < nb) ? g_bsum[tid] : 0;
    sh[tid] = v;
    __syncthreads();
    for (int off = 1; off < 256; off <<= 1) {
        int t = (tid >= off) ? sh[tid - off] : 0;
        __syncthreads();
        sh[tid] += t;
        __syncthreads();
    }
    if (tid < nb) g_bsum[tid] = sh[tid] - v;
}
__global__ void k_scan3(int N) {
    __shared__ int sh[256];
    const int tid = threadIdx.x;
    const int base = blockIdx.x * SCHUNK + tid * 8;
    int d[8];
    int s = 0;
#pragma unroll
    for (int i = 0; i < 8; i++) {
        int idx = base + i;
        d[i] = (idx < N) ? g_deg[idx] : 0;
        s += d[i];
    }
    sh[tid] = s;
    __syncthreads();
    for (int off = 1; off < 256; off <<= 1) {
        int v = (tid >= off) ? sh[tid - off] : 0;
        __syncthreads();
        sh[tid] += v;
        __syncthreads();
    }
    int run = g_bsum[blockIdx.x] + sh[tid] - s;
#pragma unroll
    for (int i = 0; i < 8; i++) {
        int idx = base + i;
        if (idx < N) {
            g_ptr[idx] = run;
            g_cur[idx] = run;
            run += d[i];
            if (idx == N - 1) g_ptr[N] = run;
        }
    }
}
__global__ void k_fill_csr(const int* __restrict__ src, const int* __restrict__ dst,
                           int E, int N) {
    int e = blockIdx.x * blockDim.x + threadIdx.x;
    if (e >= E) return;
    unsigned s = (unsigned)src[e], d = (unsigned)dst[e];
    if (s >= (unsigned)N || d >= (unsigned)N) return;
    int pos = atomicAdd(&g_cur[d], 1);
    if (pos < MAXE) g_csrc[pos] = (int)s;
}

// ---------------- merged setup (R13): w4l fold + pool zero + W1 convert ----
__global__ void k_setup(const float* __restrict__ W4, const float* __restrict__ Wl,
                        const float* __restrict__ b4, const float* __restrict__ bl,
                        const float* __restrict__ W1, int K, int G, int PZ) {
    const int bid = blockIdx.x;
    const int tid = threadIdx.x;
    if (bid == 0) {
        __shared__ float wl[HID * 2];
        wl[tid] = Wl[tid];
        wl[tid + 256] = Wl[tid + 256];
        __syncthreads();
        float s0 = 0.f, s1 = 0.f;
        for (int k = 0; k < HID; k++) {
            float w = W4[(size_t)tid * HID + k];
            s0 = fmaf(w, wl[k * 2 + 0], s0);
            s1 = fmaf(w, wl[k * 2 + 1], s1);
        }
        g_w4l[tid * 2 + 0] = s0;
        g_w4l[tid * 2 + 1] = s1;
        __shared__ float r0[256], r1[256];
        float b = b4[tid];
        r0[tid] = b * wl[tid * 2 + 0];
        r1[tid] = b * wl[tid * 2 + 1];
        __syncthreads();
        for (int st = 128; st > 0; st >>= 1) {
            if (tid < st) { r0[tid] += r0[tid + st]; r1[tid] += r1[tid + st]; }
            __syncthreads();
        }
        if (tid == 0) {
            g_w4l[HID * 2 + 0] = r0[0] + bl[0];
            g_w4l[HID * 2 + 1] = r1[0] + bl[1];
        }
    } else if (bid <= PZ) {
        int t = (bid - 1) * 256 + tid;
        if (t < G * 2) g_pool[t] = 0.f;
        if (t < G) g_cnt[t] = 0.f;
    } else {
        int n = bid - PZ - 1;   // 0..255
        if (n < HID && tid < K1P)
            g_wh[(size_t)n * K1P + tid] =
                (tid < K) ? __float2half(W1[(size_t)tid * HID + n]) : __float2half(0.f);
    }
}

// ---------------- W (256x256) -> g_wh[n][256] fp16 transpose ---------------
__global__ void k_cvtW(const float* __restrict__ W) {
    __shared__ float t[32][33];
    const int bx = blockIdx.x * 32;
    const int by = blockIdx.y * 32;
    const int tx = threadIdx.x, ty = threadIdx.y;   // 32 x 8
    for (int i = ty; i < 32; i += 8)
        t[i][tx] = W[(size_t)(by + i) * HID + bx + tx];
    __syncthreads();
    for (int i = ty; i < 32; i += 8)
        g_wh[(size_t)(bx + i) * HID + by + tx] = __float2half(t[tx][i]);
}

// ---------------- layer-1 input agg: g_xah = fp16(S·X) ----------------
__global__ void k_aggx(const float* __restrict__ x, int N, int K) {
    int node = blockIdx.x * 8 + (threadIdx.x >> 5);
    int lane = threadIdx.x & 31;
    if (node >= N) return;
    const bool p0 = lane < K, p1 = lane + 32 < K, p2 = lane + 64 < K;
    float dn = g_dinv[node];

    const float* xr = x + (size_t)node * K;
    float a0 = p0 ? xr[lane] * dn : 0.f;
    float a1 = p1 ? xr[lane + 32] * dn : 0.f;
    float a2 = p2 ? xr[lane + 64] * dn : 0.f;

    const int beg = g_ptr[node], end = g_ptr[node + 1];
    int j = beg;
    for (; j + 2 <= end; j += 2) {
        int s0 = g_csrc[j], s1 = g_csrc[j + 1];
        float d0 = g_dinv[s0], d1 = g_dinv[s1];
        const float* r0 = x + (size_t)s0 * K;
        const float* r1 = x + (size_t)s1 * K;
        if (p0) { a0 = fmaf(r0[lane], d0, a0);      a0 = fmaf(r1[lane], d1, a0); }
        if (p1) { a1 = fmaf(r0[lane + 32], d0, a1); a1 = fmaf(r1[lane + 32], d1, a1); }
        if (p2) { a2 = fmaf(r0[lane + 64], d0, a2); a2 = fmaf(r1[lane + 64], d1, a2); }
    }
    for (; j < end; j++) {
        int s = g_csrc[j];
        float ds = g_dinv[s];
        const float* r = x + (size_t)s * K;
        if (p0) a0 = fmaf(r[lane], ds, a0);
        if (p1) a1 = fmaf(r[lane + 32], ds, a1);
        if (p2) a2 = fmaf(r[lane + 64], ds, a2);
    }
    __half* o = g_xah + (size_t)node * K1P;
    if (p0) o[lane] = __float2half(a0 * dn);
    if (p1) o[lane + 32] = __float2half(a1 * dn);
    {
        int c2 = lane + 64;
        if (c2 < K1P) o[c2] = __float2half(p2 ? a2 * dn : 0.f);
    }
}

// ---------------- fp16 tensor-core GEMM (m16n8k16, fp32 accum) -------------
template <int KDIM, bool HMODE>
__global__ __launch_bounds__(256, 2)
void k_mmaN(const float* __restrict__ bias, int M) {
    const __half* A = HMODE ? (const __half*)g_a : (const __half*)g_xah;

    __shared__ __half As[2][128][16];
    __shared__ __half Bs[2][128][16];

    const int tid = threadIdx.x;
    const int lane = tid & 31;
    const int warp = tid >> 5;
    const int n0 = blockIdx.x * 128;
    const int m0 = blockIdx.y * 128;
    const int wm = (warp >> 2) * 64;
    const int wn = (warp & 3) * 32;
    const int lrow = tid >> 1;
    const int lhp = (tid & 1) * 8;

    uint4 pa, pb;

#define LDG_STAGE(k0)                                                          \
    do {                                                                       \
        int gm = m0 + lrow;                                                    \
        pa = (gm < M) ? *(const uint4*)(A + (size_t)gm * KDIM + (k0) + lhp)    \
                      : make_uint4(0, 0, 0, 0);                                \
        pb = *(const uint4*)(g_wh + (size_t)(n0 + lrow) * KDIM + (k0) + lhp);  \
    } while (0)

#define STS_STAGE(buf)                                                         \
    do {                                                                       \
        if (HMODE) {                                                           \
            __half2* ap = (__half2*)&pa;                                       \
            const __half2 z = __float2half2_rn(0.f);                           \
            ap[0] = __hmax2(ap[0], z); ap[1] = __hmax2(ap[1], z);              \
            ap[2] = __hmax2(ap[2], z); ap[3] = __hmax2(ap[3], z);              \
        }                                                                      \
        *(uint4*)&As[buf][lrow][lhp] = pa;                                     \
        *(uint4*)&Bs[buf][lrow][lhp] = pb;                                     \
    } while (0)

    float c[4][4][4] = {};

    LDG_STAGE(0);
    STS_STAGE(0);
    __syncthreads();

    const int g8 = lane >> 2;
    const int kq = lane & 3;

    const int NS = KDIM / 16;
    for (int s = 0; s < NS; s++) {
        if (s + 1 < NS) LDG_STAGE((s + 1) * 16);
        const int buf = s & 1;

        unsigned af[4][4], bf[4][2];
#pragma unroll
        for (int mt = 0; mt < 4; mt++) {
            int mr = wm + mt * 16 + g8;
            af[mt][0] = *(const unsigned*)&As[buf][mr][kq * 2];
            af[mt][1] = *(const unsigned*)&As[buf][mr + 8][kq * 2];
            af[mt][2] = *(const unsigned*)&As[buf][mr][kq * 2 + 8];
            af[mt][3] = *(const unsigned*)&As[buf][mr + 8][kq * 2 + 8];
        }
#pragma unroll
        for (int nt = 0; nt < 4; nt++) {
            int nc = wn + nt * 8 + g8;
            bf[nt][0] = *(const unsigned*)&Bs[buf][nc][kq * 2];
            bf[nt][1] = *(const unsigned*)&Bs[buf][nc][kq * 2 + 8];
        }
#pragma unroll
        for (int mt = 0; mt < 4; mt++)
#pragma unroll
            for (int nt = 0; nt < 4; nt++) {
                asm volatile(
                    "mma.sync.aligned.m16n8k16.row.col.f32.f16.f16.f32 "
                    "{%0,%1,%2,%3}, {%4,%5,%6,%7}, {%8,%9}, {%0,%1,%2,%3};"
                    : "+f"(c[mt][nt][0]), "+f"(c[mt][nt][1]),
                      "+f"(c[mt][nt][2]), "+f"(c[mt][nt][3])
                    : "r"(af[mt][0]), "r"(af[mt][1]), "r"(af[mt][2]), "r"(af[mt][3]),
                      "r"(bf[nt][0]), "r"(bf[nt][1]));
            }

        if (s + 1 < NS) {
            STS_STAGE((s + 1) & 1);
            __syncthreads();
        }
    }
#undef LDG_STAGE
#undef STS_STAGE

    const int cq = kq * 2;
#pragma unroll
    for (int mt = 0; mt < 4; mt++) {
        int r0 = m0 + wm + mt * 16 + g8;
        int r1 = r0 + 8;
        if (HMODE) {
            float dn0 = (r0 < M) ? g_dinv[r0] : 0.f;
            float dn1 = (r1 < M) ? g_dinv[r1] : 0.f;
#pragma unroll
            for (int nt = 0; nt < 4; nt++) {
                int col = n0 + wn + nt * 8 + cq;
                if (r0 < M)
                    *(__half2*)(g_h + (size_t)r0 * HID + col) =
                        __floats2half2_rn(c[mt][nt][0] * dn0, c[mt][nt][1] * dn0);
                if (r1 < M)
                    *(__half2*)(g_h + (size_t)r1 * HID + col) =
                        __floats2half2_rn(c[mt][nt][2] * dn1, c[mt][nt][3] * dn1);
            }
        } else {
#pragma unroll
            for (int nt = 0; nt < 4; nt++) {
                int col = n0 + wn + nt * 8 + cq;
                float bc0 = bias[col], bc1 = bias[col + 1];
                if (r0 < M)
                    *(__half2*)(g_a + (size_t)r0 * HID + col) =
                        __floats2half2_rn(c[mt][nt][0] + bc0, c[mt][nt][1] + bc1);
                if (r1 < M)
                    *(__half2*)(g_a + (size_t)r1 * HID + col) =
                        __floats2half2_rn(c[mt][nt][2] + bc0, c[mt][nt][3] + bc1);
            }
        }
    }
}

// ---------------- gather helper ----------------
__device__ __forceinline__ void h8_acc(uint4 v, float* a) {
    const __half2* p = (const __half2*)&v;
#pragma unroll
    for (int i = 0; i < 4; i++) {
        float2 f = __half22float2(p[i]);
        a[i * 2] += f.x;
        a[i * 2 + 1] += f.y;
    }
}

// ---------------- FUSED layer 3: gather(a2) + relu + MMA(W3) + *dinv -------
// Block = 64 nodes x full 256 N. A-tile gathered into SMEM once per node.
// Reads g_h (h2s) + b2 + g_wh (W3); writes g_a = h3*dinv (fp16).
__global__ __launch_bounds__(256, 2)
void k_fused3(const float* __restrict__ b2, int N) {
    __shared__ __half As[64][264];     // 64 rows x K=256 (+8 pad)
    __shared__ __half Bs[256][16];     // n x k-stage

    const int tid = threadIdx.x;
    const int lane = tid & 31;
    const int warp = tid >> 5;
    const int m0 = blockIdx.x * 64;
    const int c = lane * 8;

    float4 bb0 = *(const float4*)(b2 + c);
    float4 bb1 = *(const float4*)(b2 + c + 4);
    float bv[8] = {bb0.x, bb0.y, bb0.z, bb0.w, bb1.x, bb1.y, bb1.z, bb1.w};

    // ---- gather phase: warp handles 8 node rows ----
    for (int i = 0; i < 8; i++) {
        int node = m0 + warp * 8 + i;
        __half2 hh[4];
        if (node < N) {
            float acc[8] = {};
            h8_acc(*(const uint4*)(g_h + (size_t)node * HID + c), acc);
            int j = g_ptr[node];
            const int e = g_ptr[node + 1];
            for (; j + 4 <= e; j += 4) {
                int s0 = g_csrc[j], s1 = g_csrc[j + 1], s2 = g_csrc[j + 2], s3 = g_csrc[j + 3];
                uint4 v0 = *(const uint4*)(g_h + (size_t)s0 * HID + c);
                uint4 v1 = *(const uint4*)(g_h + (size_t)s1 * HID + c);
                uint4 v2 = *(const uint4*)(g_h + (size_t)s2 * HID + c);
                uint4 v3 = *(const uint4*)(g_h + (size_t)s3 * HID + c);
                h8_acc(v0, acc); h8_acc(v1, acc); h8_acc(v2, acc); h8_acc(v3, acc);
            }
            for (; j < e; j++)
                h8_acc(*(const uint4*)(g_h + (size_t)g_csrc[j] * HID + c), acc);
            float dn = g_dinv[node];
#pragma unroll
            for (int k = 0; k < 4; k++)
                hh[k] = __floats2half2_rn(
                    fmaxf(fmaf(acc[k * 2], dn, bv[k * 2]), 0.f),
                    fmaxf(fmaf(acc[k * 2 + 1], dn, bv[k * 2 + 1]), 0.f));
        } else {
            hh[0] = hh[1] = hh[2] = hh[3] = __float2half2_rn(0.f);
        }
        *(uint4*)&As[warp * 8 + i][c] = *(const uint4*)hh;
    }

    // ---- MMA phase: 64x256 tile, warp tile 32x64 (2m x 8n of m16n8) ----
    const int g8 = lane >> 2;
    const int kq = lane & 3;
    const int wm = (warp >> 2) * 32;   // 0 / 32
    const int wn = (warp & 3) * 64;    // 0 / 64 / 128 / 192

    float cc[2][8][4] = {};

    for (int s = 0; s < HID / 16; s++) {
        __syncthreads();   // also orders gather stores before first As reads
        {
            const __half* wrow = g_wh + (size_t)tid * HID + s * 16;
            *(uint4*)&Bs[tid][0] = *(const uint4*)(wrow);
            *(uint4*)&Bs[tid][8] = *(const uint4*)(wrow + 8);
        }
        __syncthreads();

        unsigned af[2][4], bf[8][2];
        const int kc = s * 16 + kq * 2;
#pragma unroll
        for (int mt = 0; mt < 2; mt++) {
            int mr = wm + mt * 16 + g8;
            af[mt][0] = *(const unsigned*)&As[mr][kc];
            af[mt][1] = *(const unsigned*)&As[mr + 8][kc];
            af[mt][2] = *(const unsigned*)&As[mr][kc + 8];
            af[mt][3] = *(const unsigned*)&As[mr + 8][kc + 8];
        }
#pragma unroll
        for (int nt = 0; nt < 8; nt++) {
            int nc = wn + nt * 8 + g8;
            bf[nt][0] = *(const unsigned*)&Bs[nc][kq * 2];
            bf[nt][1] = *(const unsigned*)&Bs[nc][kq * 2 + 8];
        }
#pragma unroll
        for (int mt = 0; mt < 2; mt++)
#pragma unroll
            for (int nt = 0; nt < 8; nt++) {
                asm volatile(
                    "mma.sync.aligned.m16n8k16.row.col.f32.f16.f16.f32 "
                    "{%0,%1,%2,%3}, {%4,%5,%6,%7}, {%8,%9}, {%0,%1,%2,%3};"
                    : "+f"(cc[mt][nt][0]), "+f"(cc[mt][nt][1]),
                      "+f"(cc[mt][nt][2]), "+f"(cc[mt][nt][3])
                    : "r"(af[mt][0]), "r"(af[mt][1]), "r"(af[mt][2]), "r"(af[mt][3]),
                      "r"(bf[nt][0]), "r"(bf[nt][1]));
            }
    }

    // ---- epilogue: g_a = h3 * dinv ----
    const int cq = kq * 2;
#pragma unroll
    for (int mt = 0; mt < 2; mt++) {
        int r0 = m0 + wm + mt * 16 + g8;
        int r1 = r0 + 8;
        float dn0 = (r0 < N) ? g_dinv[r0] : 0.f;
        float dn1 = (r1 < N) ? g_dinv[r1] : 0.f;
#pragma unroll
        for (int nt = 0; nt < 8; nt++) {
            int col = wn + nt * 8 + cq;
            if (r0 < N)
                *(__half2*)(g_a + (size_t)r0 * HID + col) =
                    __floats2half2_rn(cc[mt][nt][0] * dn0, cc[mt][nt][1] * dn0);
            if (r1 < N)
                *(__half2*)(g_a + (size_t)r1 * HID + col) =
                    __floats2half2_rn(cc[mt][nt][2] * dn1, cc[mt][nt][3] * dn1);
        }
    }
}

// ---------------- fused L3-agg + folded layer 4 (reads g_a): 2 nodes/warp --
__global__ void k_gemv4f(const float* __restrict__ b3, int N) {
    __shared__ float w4l[HID * 2];
    const int tid = threadIdx.x;   // 256
    w4l[tid] = g_w4l[tid];
    w4l[tid + 256] = g_w4l[tid + 256];
    __syncthreads();
    int warp = tid >> 5;
    int lane = tid & 31;
    int n0 = blockIdx.x * 16 + warp * 2;
    if (n0 >= N) return;
    int n1 = n0 + 1;
    bool has1 = n1 < N;
    const int c = lane * 8;

    float acc0[8] = {}, acc1[8] = {};
    h8_acc(*(const uint4*)(g_a + (size_t)n0 * HID + c), acc0);
    if (has1) h8_acc(*(const uint4*)(g_a + (size_t)n1 * HID + c), acc1);

    int j0 = g_ptr[n0];
    int e0 = g_ptr[n0 + 1];
    int j1 = e0;
    int e1 = has1 ? g_ptr[n1 + 1] : e0;

    while (j0 < e0 || j1 < e1) {
        bool p0 = j0 < e0, p1 = j1 < e1;
        uint4 v0, v1;
        if (p0) v0 = *(const uint4*)(g_a + (size_t)g_csrc[j0] * HID + c);
        if (p1) v1 = *(const uint4*)(g_a + (size_t)g_csrc[j1] * HID + c);
        if (p0) { h8_acc(v0, acc0); j0++; }
        if (p1) { h8_acc(v1, acc1); j1++; }
    }

    float4 bb0 = *(const float4*)(b3 + c);
    float4 bb1 = *(const float4*)(b3 + c + 4);
    float bv[8] = {bb0.x, bb0.y, bb0.z, bb0.w, bb1.x, bb1.y, bb1.z, bb1.w};
    const float* w = w4l + c * 2;

    float s00 = 0.f, s01 = 0.f, s10 = 0.f, s11 = 0.f;
    float dn0 = g_dinv[n0];
    float dn1 = has1 ? g_dinv[n1] : 0.f;
#pragma unroll
    for (int i = 0; i < 8; i++) {
        float a0 = fmaxf(fmaf(acc0[i], dn0, bv[i]), 0.f);
        float a1 = fmaxf(fmaf(acc1[i], dn1, bv[i]), 0.f);
        s00 = fmaf(a0, w[i * 2 + 0], s00);
        s01 = fmaf(a0, w[i * 2 + 1], s01);
        s10 = fmaf(a1, w[i * 2 + 0], s10);
        s11 = fmaf(a1, w[i * 2 + 1], s11);
    }
#pragma unroll
    for (int off = 16; off > 0; off >>= 1) {
        s00 += __shfl_down_sync(0xffffffffu, s00, off);
        s01 += __shfl_down_sync(0xffffffffu, s01, off);
        s10 += __shfl_down_sync(0xffffffffu, s10, off);
        s11 += __shfl_down_sync(0xffffffffu, s11, off);
    }
    if (lane == 0) {
        *(float2*)(g_hs2 + (size_t)n0 * 2) = make_float2(s00 * dn0, s01 * dn0);
        if (has1)
            *(float2*)(g_hs2 + (size_t)n1 * 2) = make_float2(s10 * dn1, s11 * dn1);
    }
}

// ---------------- layer-4 agg (2 cols) fused with mean-pool ----------------
__global__ void k_agg2_pool(const int* __restrict__ batch, int N, int G) {
    int node = blockIdx.x * blockDim.x + threadIdx.x;
    if (node >= N) return;
    float2 acc = *(const float2*)(g_hs2 + (size_t)node * 2);
    const int beg = g_ptr[node], end = g_ptr[node + 1];
    int j = beg;
    for (; j + 4 <= end; j += 4) {
        int s0 = g_csrc[j], s1 = g_csrc[j + 1], s2 = g_csrc[j + 2], s3 = g_csrc[j + 3];
        float2 v0 = *(const float2*)(g_hs2 + (size_t)s0 * 2);
        float2 v1 = *(const float2*)(g_hs2 + (size_t)s1 * 2);
        float2 v2 = *(const float2*)(g_hs2 + (size_t)s2 * 2);
        float2 v3 = *(const float2*)(g_hs2 + (size_t)s3 * 2);
        acc.x += v0.x + v1.x + v2.x + v3.x;
        acc.y += v0.y + v1.y + v2.y + v3.y;
    }
    for (; j < end; j++) {
        float2 v = *(const float2*)(g_hs2 + (size_t)g_csrc[j] * 2);
        acc.x += v.x; acc.y += v.y;
    }
    float dn = g_dinv[node];
    unsigned g = (unsigned)batch[node];
    if (g >= (unsigned)G) return;
    float* p = g_pool + (size_t)g * 2;
    asm volatile("red.global.add.v2.f32 [%0], {%1, %2};"
                 :: "l"(p), "f"(acc.x * dn), "f"(acc.y * dn) : "memory");
    atomicAdd(&g_cnt[g], 1.f);
}

__global__ void k_head2(float* __restrict__ out, int G) {
    int g = blockIdx.x * blockDim.x + threadIdx.x;
    if (g >= G) return;
    float cn = fmaxf(g_cnt[g], 1.f);
    out[g * 2 + 0] = g_pool[g * 2 + 0] / cn + g_w4l[HID * 2 + 0];
    out[g * 2 + 1] = g_pool[g * 2 + 1] / cn + g_w4l[HID * 2 + 1];
}

// ---------------------------------------------------------------------------
extern "C" void kernel_launch(void* const* d_in, const int* in_sizes, int n_in,
                              void* d_out, int out_size) {
    const float* x   = (const float*)d_in[0];
    const int*   ei  = (const int*)d_in[1];
    const int*   bat = (const int*)d_in[2];
    const float* W1 = (const float*)d_in[3];
    const float* b1 = (const float*)d_in[4];
    const float* W2 = (const float*)d_in[5];
    const float* b2 = (const float*)d_in[6];
    const float* W3 = (const float*)d_in[7];
    const float* b3 = (const float*)d_in[8];
    const float* W4 = (const float*)d_in[9];
    const float* b4 = (const float*)d_in[10];
    const float* Wl = (const float*)d_in[11];
    const float* bl = (const float*)d_in[12];
    float* out = (float*)d_out;

    const int N  = in_sizes[2];
    const int E  = in_sizes[1] / 2;
    const int K1 = in_sizes[0] / N;
    const int G  = out_size / 2;

    const int* src = ei;
    const int* dst = ei + E;

    const int TB = 256;
    const int nScanBlocks = (N + SCHUNK - 1) / SCHUNK;
    const int PZ = (G * 2 + 255) / 256;

    dim3 gemmGrid(HID / 128, (N + 127) / 128);
    dim3 cvtGrid(HID / 32, HID / 32), cvtBlk(32, 8);
    const unsigned aggGrid = (unsigned)((N + 15) / 16);

    // ---- CSR build + setup (R13 structure) ----
    k_zero_deg<<<(N + TB - 1) / TB, TB>>>(N);
    k_count_deg<<<(E + TB - 1) / TB, TB>>>(dst, E, N);
    k_scan1<<<nScanBlocks, 256>>>(N);
    k_scan2<<<1, 256>>>(nScanBlocks);
    k_scan3<<<nScanBlocks, 256>>>(N);
    k_fill_csr<<<(E + TB - 1) / TB, TB>>>(src, dst, E, N);
    k_setup<<<1 + PZ + HID, 256>>>(W4, Wl, b4, bl, W1, K1, G, PZ);

    // ---- layer 1 (commuted: agg X -> fp16 MMA with bias epilogue) ----
    k_aggx<<<(N + 7) / 8, 256>>>(x, N, K1);
    k_mmaN<K1P, false><<<gemmGrid, 256>>>(b1, N);
    // ---- layer 2 MMA ----
    k_cvtW<<<cvtGrid, cvtBlk>>>(W2);
    k_mmaN<HID, true><<<gemmGrid, 256>>>(nullptr, N);
    // ---- FUSED layer 3: gather(b2) + relu + MMA(W3) -> g_a ----
    k_cvtW<<<cvtGrid, cvtBlk>>>(W3);
    k_fused3<<<(N + 63) / 64, 256>>>(b2, N);
    // ---- fused L3-agg + folded layer 4, pool, head ----
    k_gemv4f<<<aggGrid, 256>>>(b3, N);
    k_agg2_pool<<<(N + TB - 1) / TB, TB>>>(bat, N, G);
    k_head2<<<(G + TB - 1) / TB, TB>>>(out, G);
}

// round 16
// speedup vs baseline: 1.0653x; 1.0653x over previous
#include <cuda_runtime.h>
#include <cuda_fp16.h>
#include <cstdint>

// ---------------------------------------------------------------------------
// GCN pipeline (S = D^-1/2 (A+I) D^-1/2):  [R13 structure — fusions reverted]
//  L1 (commuted): xah = fp16(S·xh) padded K=80 ; a1 = xah@W1 + b1 (fp16 MMA)
//  L2: h2 = relu(a1)@W2 * dinv (fp16 MMA) -> g_h ; a2 = dinv*sum(h2)+b2 -> g_a
//  L3: h3 = relu(a2)@W3 * dinv (fp16 MMA) -> g_h
//  L4 folded + fused with L3 agg (gemv4f), then mean-pool + bias fold.
// New vs R13: x pre-converted to fp16 (halves L1 gather bytes), self-cleaning
// fill_csr (drops zero_deg launch), W2+W3 converted in one launch.
// ---------------------------------------------------------------------------

#define MAXN 100000
#define MAXE 400000
#define HID  256
#define K1P  80
#define MAXG 4096
#define SCHUNK 2048

__device__ __half g_h[(size_t)MAXN * HID];
__device__ __half g_a[(size_t)MAXN * HID];
__device__ __half g_wh1[(size_t)HID * K1P];
__device__ __half g_wh2[(size_t)HID * HID];
__device__ __half g_wh3[(size_t)HID * HID];
__device__ __half g_xh[(size_t)MAXN * 69];    // fp16 copy of x
__device__ __half g_xah[(size_t)MAXN * K1P];
__device__ float  g_hs2[(size_t)MAXN * 2];
__device__ float  g_dinv[MAXN];
__device__ int    g_deg[MAXN];                // re-zeroed by fill_csr each run
__device__ int    g_ptr[MAXN + 1];
__device__ int    g_cur[MAXN];
__device__ int    g_csrc[MAXE];
__device__ int    g_bsum[256];
__device__ float  g_w4l[HID * 2 + 2];
__device__ float  g_pool[(size_t)MAXG * 2];
__device__ float  g_cnt[MAXG];

// ---------------- CSR build ----------------
__global__ void k_count_deg(const int* __restrict__ dst, int E, int N) {
    int e = blockIdx.x * blockDim.x + threadIdx.x;
    if (e < E) {
        unsigned d = (unsigned)dst[e];
        if (d < (unsigned)N) atomicAdd(&g_deg[d], 1);
    }
}
__global__ void k_scan1(int N) {
    __shared__ int sh[256];
    const int tid = threadIdx.x;
    const int base = blockIdx.x * SCHUNK + tid * 8;
    int s = 0;
#pragma unroll
    for (int i = 0; i < 8; i++) {
        int idx = base + i;
        if (idx < N) {
            int d = g_deg[idx];
            s += d;
            g_dinv[idx] = rsqrtf((float)d + 1.f);
        }
    }
    sh[tid] = s;
    __syncthreads();
    for (int off = 1; off < 256; off <<= 1) {
        int v = (tid >= off) ? sh[tid - off] : 0;
        __syncthreads();
        sh[tid] += v;
        __syncthreads();
    }
    if (tid == 255) g_bsum[blockIdx.x] = sh[255];
}
__global__ void k_scan2(int nb) {
    __shared__ int sh[256];
    const int tid = threadIdx.x;
    int v = (tid < nb) ? g_bsum[tid] : 0;
    sh[tid] = v;
    __syncthreads();
    for (int off = 1; off < 256; off <<= 1) {
        int t = (tid >= off) ? sh[tid - off] : 0;
        __syncthreads();
        sh[tid] += t;
        __syncthreads();
    }
    if (tid < nb) g_bsum[tid] = sh[tid] - v;
}
__global__ void k_scan3(int N) {
    __shared__ int sh[256];
    const int tid = threadIdx.x;
    const int base = blockIdx.x * SCHUNK + tid * 8;
    int d[8];
    int s = 0;
#pragma unroll
    for (int i = 0; i < 8; i++) {
        int idx = base + i;
        d[i] = (idx < N) ? g_deg[idx] : 0;
        s += d[i];
    }
    sh[tid] = s;
    __syncthreads();
    for (int off = 1; off < 256; off <<= 1) {
        int v = (tid >= off) ? sh[tid - off] : 0;
        __syncthreads();
        sh[tid] += v;
        __syncthreads();
    }
    int run = g_bsum[blockIdx.x] + sh[tid] - s;
#pragma unroll
    for (int i = 0; i < 8; i++) {
        int idx = base + i;
        if (idx < N) {
            g_ptr[idx] = run;
            g_cur[idx] = run;
            run += d[i];
            if (idx == N - 1) g_ptr[N] = run;
        }
    }
}
// fill CSR; also re-zero g_deg for the next graph replay (self-cleaning)
__global__ void k_fill_csr(const int* __restrict__ src, const int* __restrict__ dst,
                           int E, int N) {
    int e = blockIdx.x * blockDim.x + threadIdx.x;
    if (e < N) g_deg[e] = 0;
    if (e >= E) return;
    unsigned s = (unsigned)src[e], d = (unsigned)dst[e];
    if (s >= (unsigned)N || d >= (unsigned)N) return;
    int pos = atomicAdd(&g_cur[d], 1);
    if (pos < MAXE) g_csrc[pos] = (int)s;
}

// ---------------- x -> fp16 copy ----------------
__global__ void k_cvtx(const float* __restrict__ x, int n) {
    int i = blockIdx.x * blockDim.x + threadIdx.x;
    if (i < n) g_xh[i] = __float2half(x[i]);
}

// ---------------- merged setup: w4l fold + pool zero + W1 convert ----------
__global__ void k_setup(const float* __restrict__ W4, const float* __restrict__ Wl,
                        const float* __restrict__ b4, const float* __restrict__ bl,
                        const float* __restrict__ W1, int K, int G, int PZ) {
    const int bid = blockIdx.x;
    const int tid = threadIdx.x;
    if (bid == 0) {
        __shared__ float wl[HID * 2];
        wl[tid] = Wl[tid];
        wl[tid + 256] = Wl[tid + 256];
        __syncthreads();
        float s0 = 0.f, s1 = 0.f;
        for (int k = 0; k < HID; k++) {
            float w = W4[(size_t)tid * HID + k];
            s0 = fmaf(w, wl[k * 2 + 0], s0);
            s1 = fmaf(w, wl[k * 2 + 1], s1);
        }
        g_w4l[tid * 2 + 0] = s0;
        g_w4l[tid * 2 + 1] = s1;
        __shared__ float r0[256], r1[256];
        float b = b4[tid];
        r0[tid] = b * wl[tid * 2 + 0];
        r1[tid] = b * wl[tid * 2 + 1];
        __syncthreads();
        for (int st = 128; st > 0; st >>= 1) {
            if (tid < st) { r0[tid] += r0[tid + st]; r1[tid] += r1[tid + st]; }
            __syncthreads();
        }
        if (tid == 0) {
            g_w4l[HID * 2 + 0] = r0[0] + bl[0];
            g_w4l[HID * 2 + 1] = r1[0] + bl[1];
        }
    } else if (bid <= PZ) {
        int t = (bid - 1) * 256 + tid;
        if (t < G * 2) g_pool[t] = 0.f;
        if (t < G) g_cnt[t] = 0.f;
    } else {
        int n = bid - PZ - 1;   // 0..255
        if (n < HID && tid < K1P)
            g_wh1[(size_t)n * K1P + tid] =
                (tid < K) ? __float2half(W1[(size_t)tid * HID + n]) : __float2half(0.f);
    }
}

// ---------------- W2,W3 -> g_wh2,g_wh3 fp16 transpose (one launch) ---------
__global__ void k_cvtW23(const float* __restrict__ W2, const float* __restrict__ W3) {
    __shared__ float t[32][33];
    const float* W = blockIdx.z ? W3 : W2;
    __half* out = blockIdx.z ? (__half*)g_wh3 : (__half*)g_wh2;
    const int bx = blockIdx.x * 32;
    const int by = blockIdx.y * 32;
    const int tx = threadIdx.x, ty = threadIdx.y;   // 32 x 8
    for (int i = ty; i < 32; i += 8)
        t[i][tx] = W[(size_t)(by + i) * HID + bx + tx];
    __syncthreads();
    for (int i = ty; i < 32; i += 8)
        out[(size_t)(bx + i) * HID + by + tx] = __float2half(t[tx][i]);
}

// ---------------- layer-1 input agg (fp16 x): g_xah = fp16(S·xh) -----------
__global__ void k_aggx(int N, int K) {
    int node = blockIdx.x * 8 + (threadIdx.x >> 5);
    int lane = threadIdx.x & 31;
    if (node >= N) return;
    const bool p0 = lane < K, p1 = lane + 32 < K, p2 = lane + 64 < K;
    float dn = g_dinv[node];

    const __half* xr = g_xh + (size_t)node * K;
    float a0 = p0 ? __half2float(xr[lane]) * dn : 0.f;
    float a1 = p1 ? __half2float(xr[lane + 32]) * dn : 0.f;
    float a2 = p2 ? __half2float(xr[lane + 64]) * dn : 0.f;

    const int beg = g_ptr[node], end = g_ptr[node + 1];
    int j = beg;
    for (; j + 2 <= end; j += 2) {
        int s0 = g_csrc[j], s1 = g_csrc[j + 1];
        float d0 = g_dinv[s0], d1 = g_dinv[s1];
        const __half* r0 = g_xh + (size_t)s0 * K;
        const __half* r1 = g_xh + (size_t)s1 * K;
        if (p0) { a0 = fmaf(__half2float(r0[lane]), d0, a0);
                  a0 = fmaf(__half2float(r1[lane]), d1, a0); }
        if (p1) { a1 = fmaf(__half2float(r0[lane + 32]), d0, a1);
                  a1 = fmaf(__half2float(r1[lane + 32]), d1, a1); }
        if (p2) { a2 = fmaf(__half2float(r0[lane + 64]), d0, a2);
                  a2 = fmaf(__half2float(r1[lane + 64]), d1, a2); }
    }
    for (; j < end; j++) {
        int s = g_csrc[j];
        float ds = g_dinv[s];
        const __half* r = g_xh + (size_t)s * K;
        if (p0) a0 = fmaf(__half2float(r[lane]), ds, a0);
        if (p1) a1 = fmaf(__half2float(r[lane + 32]), ds, a1);
        if (p2) a2 = fmaf(__half2float(r[lane + 64]), ds, a2);
    }
    __half* o = g_xah + (size_t)node * K1P;
    if (p0) o[lane] = __float2half(a0 * dn);
    if (p1) o[lane + 32] = __float2half(a1 * dn);
    {
        int c2 = lane + 64;
        if (c2 < K1P) o[c2] = __float2half(p2 ? a2 * dn : 0.f);
    }
}

// ---------------- fp16 tensor-core GEMM (m16n8k16, fp32 accum) -------------
// WSEL: 1 = g_wh1 (K=K1P), 2 = g_wh2, 3 = g_wh3.
template <int KDIM, bool HMODE, int WSEL>
__global__ __launch_bounds__(256, 2)
void k_mmaN(const float* __restrict__ bias, int M) {
    const __half* A = HMODE ? (const __half*)g_a : (const __half*)g_xah;
    const __half* Wt = (WSEL == 1) ? (const __half*)g_wh1
                     : (WSEL == 2) ? (const __half*)g_wh2 : (const __half*)g_wh3;

    __shared__ __half As[2][128][16];
    __shared__ __half Bs[2][128][16];

    const int tid = threadIdx.x;
    const int lane = tid & 31;
    const int warp = tid >> 5;
    const int n0 = blockIdx.x * 128;
    const int m0 = blockIdx.y * 128;
    const int wm = (warp >> 2) * 64;
    const int wn = (warp & 3) * 32;
    const int lrow = tid >> 1;
    const int lhp = (tid & 1) * 8;

    uint4 pa, pb;

#define LDG_STAGE(k0)                                                          \
    do {                                                                       \
        int gm = m0 + lrow;                                                    \
        pa = (gm < M) ? *(const uint4*)(A + (size_t)gm * KDIM + (k0) + lhp)    \
                      : make_uint4(0, 0, 0, 0);                                \
        pb = *(const uint4*)(Wt + (size_t)(n0 + lrow) * KDIM + (k0) + lhp);    \
    } while (0)

#define STS_STAGE(buf)                                                         \
    do {                                                                       \
        if (HMODE) {                                                           \
            __half2* ap = (__half2*)&pa;                                       \
            const __half2 z = __float2half2_rn(0.f);                           \
            ap[0] = __hmax2(ap[0], z); ap[1] = __hmax2(ap[1], z);              \
            ap[2] = __hmax2(ap[2], z); ap[3] = __hmax2(ap[3], z);              \
        }                                                                      \
        *(uint4*)&As[buf][lrow][lhp] = pa;                                     \
        *(uint4*)&Bs[buf][lrow][lhp] = pb;                                     \
    } while (0)

    float c[4][4][4] = {};

    LDG_STAGE(0);
    STS_STAGE(0);
    __syncthreads();

    const int g8 = lane >> 2;
    const int kq = lane & 3;

    const int NS = KDIM / 16;
    for (int s = 0; s < NS; s++) {
        if (s + 1 < NS) LDG_STAGE((s + 1) * 16);
        const int buf = s & 1;

        unsigned af[4][4], bf[4][2];
#pragma unroll
        for (int mt = 0; mt < 4; mt++) {
            int mr = wm + mt * 16 + g8;
            af[mt][0] = *(const unsigned*)&As[buf][mr][kq * 2];
            af[mt][1] = *(const unsigned*)&As[buf][mr + 8][kq * 2];
            af[mt][2] = *(const unsigned*)&As[buf][mr][kq * 2 + 8];
            af[mt][3] = *(const unsigned*)&As[buf][mr + 8][kq * 2 + 8];
        }
#pragma unroll
        for (int nt = 0; nt < 4; nt++) {
            int nc = wn + nt * 8 + g8;
            bf[nt][0] = *(const unsigned*)&Bs[buf][nc][kq * 2];
            bf[nt][1] = *(const unsigned*)&Bs[buf][nc][kq * 2 + 8];
        }
#pragma unroll
        for (int mt = 0; mt < 4; mt++)
#pragma unroll
            for (int nt = 0; nt < 4; nt++) {
                asm volatile(
                    "mma.sync.aligned.m16n8k16.row.col.f32.f16.f16.f32 "
                    "{%0,%1,%2,%3}, {%4,%5,%6,%7}, {%8,%9}, {%0,%1,%2,%3};"
                    : "+f"(c[mt][nt][0]), "+f"(c[mt][nt][1]),
                      "+f"(c[mt][nt][2]), "+f"(c[mt][nt][3])
                    : "r"(af[mt][0]), "r"(af[mt][1]), "r"(af[mt][2]), "r"(af[mt][3]),
                      "r"(bf[nt][0]), "r"(bf[nt][1]));
            }

        if (s + 1 < NS) {
            STS_STAGE((s + 1) & 1);
            __syncthreads();
        }
    }
#undef LDG_STAGE
#undef STS_STAGE

    const int cq = kq * 2;
#pragma unroll
    for (int mt = 0; mt < 4; mt++) {
        int r0 = m0 + wm + mt * 16 + g8;
        int r1 = r0 + 8;
        if (HMODE) {
            float dn0 = (r0 < M) ? g_dinv[r0] : 0.f;
            float dn1 = (r1 < M) ? g_dinv[r1] : 0.f;
#pragma unroll
            for (int nt = 0; nt < 4; nt++) {
                int col = n0 + wn + nt * 8 + cq;
                if (r0 < M)
                    *(__half2*)(g_h + (size_t)r0 * HID + col) =
                        __floats2half2_rn(c[mt][nt][0] * dn0, c[mt][nt][1] * dn0);
                if (r1 < M)
                    *(__half2*)(g_h + (size_t)r1 * HID + col) =
                        __floats2half2_rn(c[mt][nt][2] * dn1, c[mt][nt][3] * dn1);
            }
        } else {
#pragma unroll
            for (int nt = 0; nt < 4; nt++) {
                int col = n0 + wn + nt * 8 + cq;
                float bc0 = bias[col], bc1 = bias[col + 1];
                if (r0 < M)
                    *(__half2*)(g_a + (size_t)r0 * HID + col) =
                        __floats2half2_rn(c[mt][nt][0] + bc0, c[mt][nt][1] + bc1);
                if (r1 < M)
                    *(__half2*)(g_a + (size_t)r1 * HID + col) =
                        __floats2half2_rn(c[mt][nt][2] + bc0, c[mt][nt][3] + bc1);
            }
        }
    }
}

// ---------------- gather helper ----------------
__device__ __forceinline__ void h8_acc(uint4 v, float* a) {
    const __half2* p = (const __half2*)&v;
#pragma unroll
    for (int i = 0; i < 4; i++) {
        float2 f = __half22float2(p[i]);
        a[i * 2] += f.x;
        a[i * 2 + 1] += f.y;
    }
}

// ---------------- CSR agg: 2 nodes per warp ----------------
__global__ void k_agg(const float* __restrict__ bias, int N) {
    int warp = threadIdx.x >> 5;
    int lane = threadIdx.x & 31;
    int n0 = blockIdx.x * 16 + warp * 2;
    if (n0 >= N) return;
    int n1 = n0 + 1;
    bool has1 = n1 < N;
    const int c = lane * 8;

    float acc0[8] = {}, acc1[8] = {};
    h8_acc(*(const uint4*)(g_h + (size_t)n0 * HID + c), acc0);
    if (has1) h8_acc(*(const uint4*)(g_h + (size_t)n1 * HID + c), acc1);

    int j0 = g_ptr[n0];
    int e0 = g_ptr[n0 + 1];
    int j1 = e0;
    int e1 = has1 ? g_ptr[n1 + 1] : e0;

    while (j0 < e0 || j1 < e1) {
        bool p0 = j0 < e0, p1 = j1 < e1;
        uint4 v0, v1;
        if (p0) v0 = *(const uint4*)(g_h + (size_t)g_csrc[j0] * HID + c);
        if (p1) v1 = *(const uint4*)(g_h + (size_t)g_csrc[j1] * HID + c);
        if (p0) { h8_acc(v0, acc0); j0++; }
        if (p1) { h8_acc(v1, acc1); j1++; }
    }

    float4 b0 = *(const float4*)(bias + c);
    float4 b1 = *(const float4*)(bias + c + 4);
    float bv[8] = {b0.x, b0.y, b0.z, b0.w, b1.x, b1.y, b1.z, b1.w};

    {
        float dn = g_dinv[n0];
        __half2 hh[4];
#pragma unroll
        for (int i = 0; i < 4; i++)
            hh[i] = __floats2half2_rn(fmaf(acc0[i * 2], dn, bv[i * 2]),
                                      fmaf(acc0[i * 2 + 1], dn, bv[i * 2 + 1]));
        *(uint4*)(g_a + (size_t)n0 * HID + c) = *(const uint4*)hh;
    }
    if (has1) {
        float dn = g_dinv[n1];
        __half2 hh[4];
#pragma unroll
        for (int i = 0; i < 4; i++)
            hh[i] = __floats2half2_rn(fmaf(acc1[i * 2], dn, bv[i * 2]),
                                      fmaf(acc1[i * 2 + 1], dn, bv[i * 2 + 1]));
        *(uint4*)(g_a + (size_t)n1 * HID + c) = *(const uint4*)hh;
    }
}

// ---------------- fused L3 agg + folded layer 4: 2 nodes per warp ----------
__global__ void k_gemv4f(const float* __restrict__ b3, int N) {
    __shared__ float w4l[HID * 2];
    const int tid = threadIdx.x;   // 256
    w4l[tid] = g_w4l[tid];
    w4l[tid + 256] = g_w4l[tid + 256];
    __syncthreads();
    int warp = tid >> 5;
    int lane = tid & 31;
    int n0 = blockIdx.x * 16 + warp * 2;
    if (n0 >= N) return;
    int n1 = n0 + 1;
    bool has1 = n1 < N;
    const int c = lane * 8;

    float acc0[8] = {}, acc1[8] = {};
    h8_acc(*(const uint4*)(g_h + (size_t)n0 * HID + c), acc0);
    if (has1) h8_acc(*(const uint4*)(g_h + (size_t)n1 * HID + c), acc1);

    int j0 = g_ptr[n0];
    int e0 = g_ptr[n0 + 1];
    int j1 = e0;
    int e1 = has1 ? g_ptr[n1 + 1] : e0;

    while (j0 < e0 || j1 < e1) {
        bool p0 = j0 < e0, p1 = j1 < e1;
        uint4 v0, v1;
        if (p0) v0 = *(const uint4*)(g_h + (size_t)g_csrc[j0] * HID + c);
        if (p1) v1 = *(const uint4*)(g_h + (size_t)g_csrc[j1] * HID + c);
        if (p0) { h8_acc(v0, acc0); j0++; }
        if (p1) { h8_acc(v1, acc1); j1++; }
    }

    float4 bb0 = *(const float4*)(b3 + c);
    float4 bb1 = *(const float4*)(b3 + c + 4);
    float bv[8] = {bb0.x, bb0.y, bb0.z, bb0.w, bb1.x, bb1.y, bb1.z, bb1.w};
    const float* w = w4l + c * 2;

    float s00 = 0.f, s01 = 0.f, s10 = 0.f, s11 = 0.f;
    float dn0 = g_dinv[n0];
    float dn1 = has1 ? g_dinv[n1] : 0.f;
#pragma unroll
    for (int i = 0; i < 8; i++) {
        float a0 = fmaxf(fmaf(acc0[i], dn0, bv[i]), 0.f);
        float a1 = fmaxf(fmaf(acc1[i], dn1, bv[i]), 0.f);
        s00 = fmaf(a0, w[i * 2 + 0], s00);
        s01 = fmaf(a0, w[i * 2 + 1], s01);
        s10 = fmaf(a1, w[i * 2 + 0], s10);
        s11 = fmaf(a1, w[i * 2 + 1], s11);
    }
#pragma unroll
    for (int off = 16; off > 0; off >>= 1) {
        s00 += __shfl_down_sync(0xffffffffu, s00, off);
        s01 += __shfl_down_sync(0xffffffffu, s01, off);
        s10 += __shfl_down_sync(0xffffffffu, s10, off);
        s11 += __shfl_down_sync(0xffffffffu, s11, off);
    }
    if (lane == 0) {
        *(float2*)(g_hs2 + (size_t)n0 * 2) = make_float2(s00 * dn0, s01 * dn0);
        if (has1)
            *(float2*)(g_hs2 + (size_t)n1 * 2) = make_float2(s10 * dn1, s11 * dn1);
    }
}

// ---------------- layer-4 agg (2 cols) fused with mean-pool ----------------
__global__ void k_agg2_pool(const int* __restrict__ batch, int N, int G) {
    int node = blockIdx.x * blockDim.x + threadIdx.x;
    if (node >= N) return;
    float2 acc = *(const float2*)(g_hs2 + (size_t)node * 2);
    const int beg = g_ptr[node], end = g_ptr[node + 1];
    int j = beg;
    for (; j + 4 <= end; j += 4) {
        int s0 = g_csrc[j], s1 = g_csrc[j + 1], s2 = g_csrc[j + 2], s3 = g_csrc[j + 3];
        float2 v0 = *(const float2*)(g_hs2 + (size_t)s0 * 2);
        float2 v1 = *(const float2*)(g_hs2 + (size_t)s1 * 2);
        float2 v2 = *(const float2*)(g_hs2 + (size_t)s2 * 2);
        float2 v3 = *(const float2*)(g_hs2 + (size_t)s3 * 2);
        acc.x += v0.x + v1.x + v2.x + v3.x;
        acc.y += v0.y + v1.y + v2.y + v3.y;
    }
    for (; j < end; j++) {
        float2 v = *(const float2*)(g_hs2 + (size_t)g_csrc[j] * 2);
        acc.x += v.x; acc.y += v.y;
    }
    float dn = g_dinv[node];
    unsigned g = (unsigned)batch[node];
    if (g >= (unsigned)G) return;
    float* p = g_pool + (size_t)g * 2;
    asm volatile("red.global.add.v2.f32 [%0], {%1, %2};"
                 :: "l"(p), "f"(acc.x * dn), "f"(acc.y * dn) : "memory");
    atomicAdd(&g_cnt[g], 1.f);
}

__global__ void k_head2(float* __restrict__ out, int G) {
    int g = blockIdx.x * blockDim.x + threadIdx.x;
    if (g >= G) return;
    float cn = fmaxf(g_cnt[g], 1.f);
    out[g * 2 + 0] = g_pool[g * 2 + 0] / cn + g_w4l[HID * 2 + 0];
    out[g * 2 + 1] = g_pool[g * 2 + 1] / cn + g_w4l[HID * 2 + 1];
}

// ---------------------------------------------------------------------------
extern "C" void kernel_launch(void* const* d_in, const int* in_sizes, int n_in,
                              void* d_out, int out_size) {
    const float* x   = (const float*)d_in[0];
    const int*   ei  = (const int*)d_in[1];
    const int*   bat = (const int*)d_in[2];
    const float* W1 = (const float*)d_in[3];
    const float* b1 = (const float*)d_in[4];
    const float* W2 = (const float*)d_in[5];
    const float* b2 = (const float*)d_in[6];
    const float* W3 = (const float*)d_in[7];
    const float* b3 = (const float*)d_in[8];
    const float* W4 = (const float*)d_in[9];
    const float* b4 = (const float*)d_in[10];
    const float* Wl = (const float*)d_in[11];
    const float* bl = (const float*)d_in[12];
    float* out = (float*)d_out;

    const int N  = in_sizes[2];
    const int E  = in_sizes[1] / 2;
    const int K1 = in_sizes[0] / N;
    const int G  = out_size / 2;

    const int* src = ei;
    const int* dst = ei + E;

    const int TB = 256;
    const int nScanBlocks = (N + SCHUNK - 1) / SCHUNK;
    const int PZ = (G * 2 + 255) / 256;

    dim3 gemmGrid(HID / 128, (N + 127) / 128);
    dim3 cvtGrid(HID / 32, HID / 32, 2), cvtBlk(32, 8);
    const unsigned aggGrid = (unsigned)((N + 15) / 16);

    // ---- CSR build (self-cleaning fill) + x fp16 + setup ----
    k_count_deg<<<(E + TB - 1) / TB, TB>>>(dst, E, N);
    k_scan1<<<nScanBlocks, 256>>>(N);
    k_scan2<<<1, 256>>>(nScanBlocks);
    k_scan3<<<nScanBlocks, 256>>>(N);
    k_fill_csr<<<(E + TB - 1) / TB, TB>>>(src, dst, E, N);
    k_cvtx<<<(N * K1 + TB - 1) / TB, TB>>>(x, N * K1);
    k_setup<<<1 + PZ + HID, 256>>>(W4, Wl, b4, bl, W1, K1, G, PZ);
    k_cvtW23<<<cvtGrid, cvtBlk>>>(W2, W3);

    // ---- layer 1 (commuted: fp16 agg X -> fp16 MMA with bias epilogue) ----
    k_aggx<<<(N + 7) / 8, 256>>>(N, K1);
    k_mmaN<K1P, false, 1><<<gemmGrid, 256>>>(b1, N);
    // ---- layer 2 ----
    k_mmaN<HID, true, 2><<<gemmGrid, 256>>>(nullptr, N);
    k_agg<<<aggGrid, 256>>>(b2, N);
    // ---- layer 3 ----
    k_mmaN<HID, true, 3><<<gemmGrid, 256>>>(nullptr, N);
    // ---- fused L3-agg + folded layer 4, pool, head ----
    k_gemv4f<<<aggGrid, 256>>>(b3, N);
    k_agg2_pool<<<(N + TB - 1) / TB, TB>>>(bat, N, G);
    k_head2<<<(G + TB - 1) / TB, TB>>>(out, G);
}

// round 17
// speedup vs baseline: 1.1004x; 1.0330x over previous
#include <cuda_runtime.h>
#include <cuda_fp16.h>
#include <cstdint>

// ---------------------------------------------------------------------------
// GCN pipeline (S = D^-1/2 (A+I) D^-1/2):  [R13 structure]
//  L1 (commuted): xah = fp16(S·X) padded K=80 ; a1 = xah@W1 + b1 (fp16 MMA)
//  L2: h2 = relu(a1)@W2 * dinv (fp16 MMA) -> g_h ; a2 = dinv*sum(h2)+b2 -> g_a
//  L3: h3 = relu(a2)@W3 * dinv (fp16 MMA) -> g_h
//  L4 folded + fused with L3 agg (gemv4f), then mean-pool + bias fold.
// Only change vs R13: k_fill_csr re-zeros g_deg (self-cleaning), so the
// k_zero_deg launch is gone. 16 launches.
// ---------------------------------------------------------------------------

#define MAXN 100000
#define MAXE 400000
#define HID  256
#define K1P  80
#define MAXG 4096
#define SCHUNK 2048

__device__ __half g_h[(size_t)MAXN * HID];
__device__ __half g_a[(size_t)MAXN * HID];
__device__ __half g_wh[(size_t)HID * HID];
__device__ __half g_xah[(size_t)MAXN * K1P];
__device__ float  g_hs2[(size_t)MAXN * 2];
__device__ float  g_dinv[MAXN];
__device__ int    g_deg[MAXN];      // zero at load; re-zeroed by fill_csr
__device__ int    g_ptr[MAXN + 1];
__device__ int    g_cur[MAXN];
__device__ int    g_csrc[MAXE];
__device__ int    g_bsum[256];
__device__ float  g_w4l[HID * 2 + 2];
__device__ float  g_pool[(size_t)MAXG * 2];
__device__ float  g_cnt[MAXG];

// ---------------- CSR build ----------------
__global__ void k_count_deg(const int* __restrict__ dst, int E, int N) {
    int e = blockIdx.x * blockDim.x + threadIdx.x;
    if (e < E) {
        unsigned d = (unsigned)dst[e];
        if (d < (unsigned)N) atomicAdd(&g_deg[d], 1);
    }
}
__global__ void k_scan1(int N) {
    __shared__ int sh[256];
    const int tid = threadIdx.x;
    const int base = blockIdx.x * SCHUNK + tid * 8;
    int s = 0;
#pragma unroll
    for (int i = 0; i < 8; i++) {
        int idx = base + i;
        if (idx < N) {
            int d = g_deg[idx];
            s += d;
            g_dinv[idx] = rsqrtf((float)d + 1.f);
        }
    }
    sh[tid] = s;
    __syncthreads();
    for (int off = 1; off < 256; off <<= 1) {
        int v = (tid >= off) ? sh[tid - off] : 0;
        __syncthreads();
        sh[tid] += v;
        __syncthreads();
    }
    if (tid == 255) g_bsum[blockIdx.x] = sh[255];
}
__global__ void k_scan2(int nb) {
    __shared__ int sh[256];
    const int tid = threadIdx.x;
    int v = (tid < nb) ? g_bsum[tid] : 0;
    sh[tid] = v;
    __syncthreads();
    for (int off = 1; off < 256; off <<= 1) {
        int t = (tid >= off) ? sh[tid - off] : 0;
        __syncthreads();
        sh[tid] += t;
        __syncthreads();
    }
    if (tid < nb) g_bsum[tid] = sh[tid] - v;
}
__global__ void k_scan3(int N) {
    __shared__ int sh[256];
    const int tid = threadIdx.x;
    const int base = blockIdx.x * SCHUNK + tid * 8;
    int d[8];
    int s = 0;
#pragma unroll
    for (int i = 0; i < 8; i++) {
        int idx = base + i;
        d[i] = (idx < N) ? g_deg[idx] : 0;
        s += d[i];
    }
    sh[tid] = s;
    __syncthreads();
    for (int off = 1; off < 256; off <<= 1) {
        int v = (tid >= off) ? sh[tid - off] : 0;
        __syncthreads();
        sh[tid] += v;
        __syncthreads();
    }
    int run = g_bsum[blockIdx.x] + sh[tid] - s;
#pragma unroll
    for (int i = 0; i < 8; i++) {
        int idx = base + i;
        if (idx < N) {
            g_ptr[idx] = run;
            g_cur[idx] = run;
            run += d[i];
            if (idx == N - 1) g_ptr[N] = run;
        }
    }
}
// fill CSR; also re-zero g_deg for the next graph replay (self-cleaning)
__global__ void k_fill_csr(const int* __restrict__ src, const int* __restrict__ dst,
                           int E, int N) {
    int e = blockIdx.x * blockDim.x + threadIdx.x;
    if (e < N) g_deg[e] = 0;
    if (e >= E) return;
    unsigned s = (unsigned)src[e], d = (unsigned)dst[e];
    if (s >= (unsigned)N || d >= (unsigned)N) return;
    int pos = atomicAdd(&g_cur[d], 1);
    if (pos < MAXE) g_csrc[pos] = (int)s;
}

// ---------------- merged setup: w4l fold + pool zero + W1 convert ----------
__global__ void k_setup(const float* __restrict__ W4, const float* __restrict__ Wl,
                        const float* __restrict__ b4, const float* __restrict__ bl,
                        const float* __restrict__ W1, int K, int G, int PZ) {
    const int bid = blockIdx.x;
    const int tid = threadIdx.x;
    if (bid == 0) {
        __shared__ float wl[HID * 2];
        wl[tid] = Wl[tid];
        wl[tid + 256] = Wl[tid + 256];
        __syncthreads();
        float s0 = 0.f, s1 = 0.f;
        for (int k = 0; k < HID; k++) {
            float w = W4[(size_t)tid * HID + k];
            s0 = fmaf(w, wl[k * 2 + 0], s0);
            s1 = fmaf(w, wl[k * 2 + 1], s1);
        }
        g_w4l[tid * 2 + 0] = s0;
        g_w4l[tid * 2 + 1] = s1;
        __shared__ float r0[256], r1[256];
        float b = b4[tid];
        r0[tid] = b * wl[tid * 2 + 0];
        r1[tid] = b * wl[tid * 2 + 1];
        __syncthreads();
        for (int st = 128; st > 0; st >>= 1) {
            if (tid < st) { r0[tid] += r0[tid + st]; r1[tid] += r1[tid + st]; }
            __syncthreads();
        }
        if (tid == 0) {
            g_w4l[HID * 2 + 0] = r0[0] + bl[0];
            g_w4l[HID * 2 + 1] = r1[0] + bl[1];
        }
    } else if (bid <= PZ) {
        int t = (bid - 1) * 256 + tid;
        if (t < G * 2) g_pool[t] = 0.f;
        if (t < G) g_cnt[t] = 0.f;
    } else {
        int n = bid - PZ - 1;   // 0..255
        if (n < HID && tid < K1P)
            g_wh[(size_t)n * K1P + tid] =
                (tid < K) ? __float2half(W1[(size_t)tid * HID + n]) : __float2half(0.f);
    }
}

// ---------------- W (256x256) -> g_wh[n][256] fp16 transpose ---------------
__global__ void k_cvtW(const float* __restrict__ W) {
    __shared__ float t[32][33];
    const int bx = blockIdx.x * 32;
    const int by = blockIdx.y * 32;
    const int tx = threadIdx.x, ty = threadIdx.y;   // 32 x 8
    for (int i = ty; i < 32; i += 8)
        t[i][tx] = W[(size_t)(by + i) * HID + bx + tx];
    __syncthreads();
    for (int i = ty; i < 32; i += 8)
        g_wh[(size_t)(bx + i) * HID + by + tx] = __float2half(t[tx][i]);
}

// ---------------- layer-1 input agg: g_xah = fp16(S·X) ----------------
__global__ void k_aggx(const float* __restrict__ x, int N, int K) {
    int node = blockIdx.x * 8 + (threadIdx.x >> 5);
    int lane = threadIdx.x & 31;
    if (node >= N) return;
    const bool p0 = lane < K, p1 = lane + 32 < K, p2 = lane + 64 < K;
    float dn = g_dinv[node];

    const float* xr = x + (size_t)node * K;
    float a0 = p0 ? xr[lane] * dn : 0.f;
    float a1 = p1 ? xr[lane + 32] * dn : 0.f;
    float a2 = p2 ? xr[lane + 64] * dn : 0.f;

    const int beg = g_ptr[node], end = g_ptr[node + 1];
    int j = beg;
    for (; j + 2 <= end; j += 2) {
        int s0 = g_csrc[j], s1 = g_csrc[j + 1];
        float d0 = g_dinv[s0], d1 = g_dinv[s1];
        const float* r0 = x + (size_t)s0 * K;
        const float* r1 = x + (size_t)s1 * K;
        if (p0) { a0 = fmaf(r0[lane], d0, a0);      a0 = fmaf(r1[lane], d1, a0); }
        if (p1) { a1 = fmaf(r0[lane + 32], d0, a1); a1 = fmaf(r1[lane + 32], d1, a1); }
        if (p2) { a2 = fmaf(r0[lane + 64], d0, a2); a2 = fmaf(r1[lane + 64], d1, a2); }
    }
    for (; j < end; j++) {
        int s = g_csrc[j];
        float ds = g_dinv[s];
        const float* r = x + (size_t)s * K;
        if (p0) a0 = fmaf(r[lane], ds, a0);
        if (p1) a1 = fmaf(r[lane + 32], ds, a1);
        if (p2) a2 = fmaf(r[lane + 64], ds, a2);
    }
    __half* o = g_xah + (size_t)node * K1P;
    if (p0) o[lane] = __float2half(a0 * dn);
    if (p1) o[lane + 32] = __float2half(a1 * dn);
    {
        int c2 = lane + 64;
        if (c2 < K1P) o[c2] = __float2half(p2 ? a2 * dn : 0.f);
    }
}

// ---------------- fp16 tensor-core GEMM (m16n8k16, fp32 accum) -------------
template <int KDIM, bool HMODE>
__global__ __launch_bounds__(256, 2)
void k_mmaN(const float* __restrict__ bias, int M) {
    const __half* A = HMODE ? (const __half*)g_a : (const __half*)g_xah;

    __shared__ __half As[2][128][16];
    __shared__ __half Bs[2][128][16];

    const int tid = threadIdx.x;
    const int lane = tid & 31;
    const int warp = tid >> 5;
    const int n0 = blockIdx.x * 128;
    const int m0 = blockIdx.y * 128;
    const int wm = (warp >> 2) * 64;
    const int wn = (warp & 3) * 32;
    const int lrow = tid >> 1;
    const int lhp = (tid & 1) * 8;

    uint4 pa, pb;

#define LDG_STAGE(k0)                                                          \
    do {                                                                       \
        int gm = m0 + lrow;                                                    \
        pa = (gm < M) ? *(const uint4*)(A + (size_t)gm * KDIM + (k0) + lhp)    \
                      : make_uint4(0, 0, 0, 0);                                \
        pb = *(const uint4*)(g_wh + (size_t)(n0 + lrow) * KDIM + (k0) + lhp);  \
    } while (0)

#define STS_STAGE(buf)                                                         \
    do {                                                                       \
        if (HMODE) {                                                           \
            __half2* ap = (__half2*)&pa;                                       \
            const __half2 z = __float2half2_rn(0.f);                           \
            ap[0] = __hmax2(ap[0], z); ap[1] = __hmax2(ap[1], z);              \
            ap[2] = __hmax2(ap[2], z); ap[3] = __hmax2(ap[3], z);              \
        }                                                                      \
        *(uint4*)&As[buf][lrow][lhp] = pa;                                     \
        *(uint4*)&Bs[buf][lrow][lhp] = pb;                                     \
    } while (0)

    float c[4][4][4] = {};

    LDG_STAGE(0);
    STS_STAGE(0);
    __syncthreads();

    const int g8 = lane >> 2;
    const int kq = lane & 3;

    const int NS = KDIM / 16;
    for (int s = 0; s < NS; s++) {
        if (s + 1 < NS) LDG_STAGE((s + 1) * 16);
        const int buf = s & 1;

        unsigned af[4][4], bf[4][2];
#pragma unroll
        for (int mt = 0; mt < 4; mt++) {
            int mr = wm + mt * 16 + g8;
            af[mt][0] = *(const unsigned*)&As[buf][mr][kq * 2];
            af[mt][1] = *(const unsigned*)&As[buf][mr + 8][kq * 2];
            af[mt][2] = *(const unsigned*)&As[buf][mr][kq * 2 + 8];
            af[mt][3] = *(const unsigned*)&As[buf][mr + 8][kq * 2 + 8];
        }
#pragma unroll
        for (int nt = 0; nt < 4; nt++) {
            int nc = wn + nt * 8 + g8;
            bf[nt][0] = *(const unsigned*)&Bs[buf][nc][kq * 2];
            bf[nt][1] = *(const unsigned*)&Bs[buf][nc][kq * 2 + 8];
        }
#pragma unroll
        for (int mt = 0; mt < 4; mt++)
#pragma unroll
            for (int nt = 0; nt < 4; nt++) {
                asm volatile(
                    "mma.sync.aligned.m16n8k16.row.col.f32.f16.f16.f32 "
                    "{%0,%1,%2,%3}, {%4,%5,%6,%7}, {%8,%9}, {%0,%1,%2,%3};"
                    : "+f"(c[mt][nt][0]), "+f"(c[mt][nt][1]),
                      "+f"(c[mt][nt][2]), "+f"(c[mt][nt][3])
                    : "r"(af[mt][0]), "r"(af[mt][1]), "r"(af[mt][2]), "r"(af[mt][3]),
                      "r"(bf[nt][0]), "r"(bf[nt][1]));
            }

        if (s + 1 < NS) {
            STS_STAGE((s + 1) & 1);
            __syncthreads();
        }
    }
#undef LDG_STAGE
#undef STS_STAGE

    const int cq = kq * 2;
#pragma unroll
    for (int mt = 0; mt < 4; mt++) {
        int r0 = m0 + wm + mt * 16 + g8;
        int r1 = r0 + 8;
        if (HMODE) {
            float dn0 = (r0 < M) ? g_dinv[r0] : 0.f;
            float dn1 = (r1 < M) ? g_dinv[r1] : 0.f;
#pragma unroll
            for (int nt = 0; nt < 4; nt++) {
                int col = n0 + wn + nt * 8 + cq;
                if (r0 < M)
                    *(__half2*)(g_h + (size_t)r0 * HID + col) =
                        __floats2half2_rn(c[mt][nt][0] * dn0, c[mt][nt][1] * dn0);
                if (r1 < M)
                    *(__half2*)(g_h + (size_t)r1 * HID + col) =
                        __floats2half2_rn(c[mt][nt][2] * dn1, c[mt][nt][3] * dn1);
            }
        } else {
#pragma unroll
            for (int nt = 0; nt < 4; nt++) {
                int col = n0 + wn + nt * 8 + cq;
                float bc0 = bias[col], bc1 = bias[col + 1];
                if (r0 < M)
                    *(__half2*)(g_a + (size_t)r0 * HID + col) =
                        __floats2half2_rn(c[mt][nt][0] + bc0, c[mt][nt][1] + bc1);
                if (r1 < M)
                    *(__half2*)(g_a + (size_t)r1 * HID + col) =
                        __floats2half2_rn(c[mt][nt][2] + bc0, c[mt][nt][3] + bc1);
            }
        }
    }
}

// ---------------- gather helper ----------------
__device__ __forceinline__ void h8_acc(uint4 v, float* a) {
    const __half2* p = (const __half2*)&v;
#pragma unroll
    for (int i = 0; i < 4; i++) {
        float2 f = __half22float2(p[i]);
        a[i * 2] += f.x;
        a[i * 2 + 1] += f.y;
    }
}

// ---------------- CSR agg: 2 nodes per warp ----------------
__global__ void k_agg(const float* __restrict__ bias, int N) {
    int warp = threadIdx.x >> 5;
    int lane = threadIdx.x & 31;
    int n0 = blockIdx.x * 16 + warp * 2;
    if (n0 >= N) return;
    int n1 = n0 + 1;
    bool has1 = n1 < N;
    const int c = lane * 8;

    float acc0[8] = {}, acc1[8] = {};
    h8_acc(*(const uint4*)(g_h + (size_t)n0 * HID + c), acc0);
    if (has1) h8_acc(*(const uint4*)(g_h + (size_t)n1 * HID + c), acc1);

    int j0 = g_ptr[n0];
    int e0 = g_ptr[n0 + 1];
    int j1 = e0;
    int e1 = has1 ? g_ptr[n1 + 1] : e0;

    while (j0 < e0 || j1 < e1) {
        bool p0 = j0 < e0, p1 = j1 < e1;
        uint4 v0, v1;
        if (p0) v0 = *(const uint4*)(g_h + (size_t)g_csrc[j0] * HID + c);
        if (p1) v1 = *(const uint4*)(g_h + (size_t)g_csrc[j1] * HID + c);
        if (p0) { h8_acc(v0, acc0); j0++; }
        if (p1) { h8_acc(v1, acc1); j1++; }
    }

    float4 b0 = *(const float4*)(bias + c);
    float4 b1 = *(const float4*)(bias + c + 4);
    float bv[8] = {b0.x, b0.y, b0.z, b0.w, b1.x, b1.y, b1.z, b1.w};

    {
        float dn = g_dinv[n0];
        __half2 hh[4];
#pragma unroll
        for (int i = 0; i < 4; i++)
            hh[i] = __floats2half2_rn(fmaf(acc0[i * 2], dn, bv[i * 2]),
                                      fmaf(acc0[i * 2 + 1], dn, bv[i * 2 + 1]));
        *(uint4*)(g_a + (size_t)n0 * HID + c) = *(const uint4*)hh;
    }
    if (has1) {
        float dn = g_dinv[n1];
        __half2 hh[4];
#pragma unroll
        for (int i = 0; i < 4; i++)
            hh[i] = __floats2half2_rn(fmaf(acc1[i * 2], dn, bv[i * 2]),
                                      fmaf(acc1[i * 2 + 1], dn, bv[i * 2 + 1]));
        *(uint4*)(g_a + (size_t)n1 * HID + c) = *(const uint4*)hh;
    }
}

// ---------------- fused L3 agg + folded layer 4: 2 nodes per warp ----------
__global__ void k_gemv4f(const float* __restrict__ b3, int N) {
    __shared__ float w4l[HID * 2];
    const int tid = threadIdx.x;   // 256
    w4l[tid] = g_w4l[tid];
    w4l[tid + 256] = g_w4l[tid + 256];
    __syncthreads();
    int warp = tid >> 5;
    int lane = tid & 31;
    int n0 = blockIdx.x * 16 + warp * 2;
    if (n0 >= N) return;
    int n1 = n0 + 1;
    bool has1 = n1 < N;
    const int c = lane * 8;

    float acc0[8] = {}, acc1[8] = {};
    h8_acc(*(const uint4*)(g_h + (size_t)n0 * HID + c), acc0);
    if (has1) h8_acc(*(const uint4*)(g_h + (size_t)n1 * HID + c), acc1);

    int j0 = g_ptr[n0];
    int e0 = g_ptr[n0 + 1];
    int j1 = e0;
    int e1 = has1 ? g_ptr[n1 + 1] : e0;

    while (j0 < e0 || j1 < e1) {
        bool p0 = j0 < e0, p1 = j1 < e1;
        uint4 v0, v1;
        if (p0) v0 = *(const uint4*)(g_h + (size_t)g_csrc[j0] * HID + c);
        if (p1) v1 = *(const uint4*)(g_h + (size_t)g_csrc[j1] * HID + c);
        if (p0) { h8_acc(v0, acc0); j0++; }
        if (p1) { h8_acc(v1, acc1); j1++; }
    }

    float4 bb0 = *(const float4*)(b3 + c);
    float4 bb1 = *(const float4*)(b3 + c + 4);
    float bv[8] = {bb0.x, bb0.y, bb0.z, bb0.w, bb1.x, bb1.y, bb1.z, bb1.w};
    const float* w = w4l + c * 2;

    float s00 = 0.f, s01 = 0.f, s10 = 0.f, s11 = 0.f;
    float dn0 = g_dinv[n0];
    float dn1 = has1 ? g_dinv[n1] : 0.f;
#pragma unroll
    for (int i = 0; i < 8; i++) {
        float a0 = fmaxf(fmaf(acc0[i], dn0, bv[i]), 0.f);
        float a1 = fmaxf(fmaf(acc1[i], dn1, bv[i]), 0.f);
        s00 = fmaf(a0, w[i * 2 + 0], s00);
        s01 = fmaf(a0, w[i * 2 + 1], s01);
        s10 = fmaf(a1, w[i * 2 + 0], s10);
        s11 = fmaf(a1, w[i * 2 + 1], s11);
    }
#pragma unroll
    for (int off = 16; off > 0; off >>= 1) {
        s00 += __shfl_down_sync(0xffffffffu, s00, off);
        s01 += __shfl_down_sync(0xffffffffu, s01, off);
        s10 += __shfl_down_sync(0xffffffffu, s10, off);
        s11 += __shfl_down_sync(0xffffffffu, s11, off);
    }
    if (lane == 0) {
        *(float2*)(g_hs2 + (size_t)n0 * 2) = make_float2(s00 * dn0, s01 * dn0);
        if (has1)
            *(float2*)(g_hs2 + (size_t)n1 * 2) = make_float2(s10 * dn1, s11 * dn1);
    }
}

// ---------------- layer-4 agg (2 cols) fused with mean-pool ----------------
__global__ void k_agg2_pool(const int* __restrict__ batch, int N, int G) {
    int node = blockIdx.x * blockDim.x + threadIdx.x;
    if (node >= N) return;
    float2 acc = *(const float2*)(g_hs2 + (size_t)node * 2);
    const int beg = g_ptr[node], end = g_ptr[node + 1];
    int j = beg;
    for (; j + 4 <= end; j += 4) {
        int s0 = g_csrc[j], s1 = g_csrc[j + 1], s2 = g_csrc[j + 2], s3 = g_csrc[j + 3];
        float2 v0 = *(const float2*)(g_hs2 + (size_t)s0 * 2);
        float2 v1 = *(const float2*)(g_hs2 + (size_t)s1 * 2);
        float2 v2 = *(const float2*)(g_hs2 + (size_t)s2 * 2);
        float2 v3 = *(const float2*)(g_hs2 + (size_t)s3 * 2);
        acc.x += v0.x + v1.x + v2.x + v3.x;
        acc.y += v0.y + v1.y + v2.y + v3.y;
    }
    for (; j < end; j++) {
        float2 v = *(const float2*)(g_hs2 + (size_t)g_csrc[j] * 2);
        acc.x += v.x; acc.y += v.y;
    }
    float dn = g_dinv[node];
    unsigned g = (unsigned)batch[node];
    if (g >= (unsigned)G) return;
    float* p = g_pool + (size_t)g * 2;
    asm volatile("red.global.add.v2.f32 [%0], {%1, %2};"
                 :: "l"(p), "f"(acc.x * dn), "f"(acc.y * dn) : "memory");
    atomicAdd(&g_cnt[g], 1.f);
}

__global__ void k_head2(float* __restrict__ out, int G) {
    int g = blockIdx.x * blockDim.x + threadIdx.x;
    if (g >= G) return;
    float cn = fmaxf(g_cnt[g], 1.f);
    out[g * 2 + 0] = g_pool[g * 2 + 0] / cn + g_w4l[HID * 2 + 0];
    out[g * 2 + 1] = g_pool[g * 2 + 1] / cn + g_w4l[HID * 2 + 1];
}

// ---------------------------------------------------------------------------
extern "C" void kernel_launch(void* const* d_in, const int* in_sizes, int n_in,
                              void* d_out, int out_size) {
    const float* x   = (const float*)d_in[0];
    const int*   ei  = (const int*)d_in[1];
    const int*   bat = (const int*)d_in[2];
    const float* W1 = (const float*)d_in[3];
    const float* b1 = (const float*)d_in[4];
    const float* W2 = (const float*)d_in[5];
    const float* b2 = (const float*)d_in[6];
    const float* W3 = (const float*)d_in[7];
    const float* b3 = (const float*)d_in[8];
    const float* W4 = (const float*)d_in[9];
    const float* b4 = (const float*)d_in[10];
    const float* Wl = (const float*)d_in[11];
    const float* bl = (const float*)d_in[12];
    float* out = (float*)d_out;

    const int N  = in_sizes[2];
    const int E  = in_sizes[1] / 2;
    const int K1 = in_sizes[0] / N;
    const int G  = out_size / 2;

    const int* src = ei;
    const int* dst = ei + E;

    const int TB = 256;
    const int nScanBlocks = (N + SCHUNK - 1) / SCHUNK;
    const int PZ = (G * 2 + 255) / 256;

    dim3 gemmGrid(HID / 128, (N + 127) / 128);
    dim3 cvtGrid(HID / 32, HID / 32), cvtBlk(32, 8);
    const unsigned aggGrid = (unsigned)((N + 15) / 16);

    // ---- CSR build (self-cleaning fill) + setup ----
    k_count_deg<<<(E + TB - 1) / TB, TB>>>(dst, E, N);
    k_scan1<<<nScanBlocks, 256>>>(N);
    k_scan2<<<1, 256>>>(nScanBlocks);
    k_scan3<<<nScanBlocks, 256>>>(N);
    k_fill_csr<<<(E + TB - 1) / TB, TB>>>(src, dst, E, N);
    k_setup<<<1 + PZ + HID, 256>>>(W4, Wl, b4, bl, W1, K1, G, PZ);

    // ---- layer 1 (commuted: agg X -> fp16 MMA with bias epilogue) ----
    k_aggx<<<(N + 7) / 8, 256>>>(x, N, K1);
    k_mmaN<K1P, false><<<gemmGrid, 256>>>(b1, N);
    // ---- layer 2 ----
    k_cvtW<<<cvtGrid, cvtBlk>>>(W2);
    k_mmaN<HID, true><<<gemmGrid, 256>>>(nullptr, N);
    k_agg<<<aggGrid, 256>>>(b2, N);
    // ---- layer 3 ----
    k_cvtW<<<cvtGrid, cvtBlk>>>(W3);
    k_mmaN<HID, true><<<gemmGrid, 256>>>(nullptr, N);
    // ---- fused L3-agg + folded layer 4, pool, head ----
    k_gemv4f<<<aggGrid, 256>>>(b3, N);
    k_agg2_pool<<<(N + TB - 1) / TB, TB>>>(bat, N, G);
    k_head2<<<(G + TB - 1) / TB, TB>>>(out, G);
}